// round 12
// baseline (speedup 1.0000x reference)
#include <cuda_runtime.h>
#include <cstdint>

#define BB 4
#define CC 4
#define HH 96
#define WW 96
#define HW (HH*WW)
#define CSZ 8             // cluster size = slices per image
#define SR 12             // rows per slice
#define NTHR 768
#define NWARP (NTHR/32)
#define NBLK (BB*CSZ)
#define NSPAN (SR*WW/32)  // 36 ballot spans per slice

__device__ int g_fwd[BB];        // zero at load; last ticket resets
__device__ int g_bwd[BB];
__device__ unsigned g_tick;

#define CLUSTER_SYNC() do { \
    asm volatile("barrier.cluster.arrive.aligned;" ::: "memory"); \
    asm volatile("barrier.cluster.wait.aligned;" ::: "memory"); } while (0)

__device__ __forceinline__ unsigned smem_u32(const void* p) {
    unsigned a;
    asm("{ .reg .u64 t; cvta.to.shared.u64 t, %1; cvt.u32.u64 %0, t; }"
        : "=r"(a) : "l"(p));
    return a;
}
__device__ __forceinline__ unsigned cluster_rank() {
    unsigned r; asm("mov.u32 %0, %%cluster_ctarank;" : "=r"(r)); return r;
}
__device__ __forceinline__ void st_cluster_u64(unsigned local_addr, unsigned rank,
                                               unsigned long long v) {
    unsigned ra;
    asm("mapa.shared::cluster.u32 %0, %1, %2;" : "=r"(ra) : "r"(local_addr), "r"(rank));
    asm volatile("st.shared::cluster.u64 [%0], %1;" :: "r"(ra), "l"(v) : "memory");
}

// horizontal min-plus with sound early exit: d2 = min_jp (j-jp)^2 + g[jp]^2
__device__ __forceinline__ int hmin(const unsigned char* g, int j) {
    int g0 = g[j];
    int best = g0 * g0;
    #pragma unroll 1
    for (int r = 1; r < WW; r++) {
        int rr = r * r;
        if (rr >= best) break;
        if (j - r >= 0) { int a = g[j - r]; best = min(best, rr + a*a); }
        if (j + r < WW) { int a = g[j + r]; best = min(best, rr + a*a); }
    }
    return best;
}

__device__ __forceinline__ int amax4(float v0, float v1, float v2, float v3) {
    int c = 0; float b = v0;
    if (v1 > b) { b = v1; c = 1; }
    if (v2 > b) { b = v2; c = 2; }
    if (v3 > b) { b = v3; c = 3; }
    return c;
}

__global__ __launch_bounds__(NTHR, 1) __cluster_dims__(CSZ, 1, 1)
void k_all(const float* __restrict__ outp, const int* __restrict__ tgt,
           float* __restrict__ out) {
    __shared__ unsigned char labP[(SR+2)*WW];
    __shared__ unsigned char labT[(SR+2)*WW];
    // full-image row-major masks: rmPT[row*3 + word] = P bits (lo32) | T bits (hi32)
    __shared__ unsigned long long rmPT[HH*3];
    __shared__ unsigned char gPr[SR*WW];
    __shared__ unsigned char gTr[SR*WW];
    __shared__ int redF[NWARP], redB[NWARP];

    const int bb  = blockIdx.x;
    const int b   = bb / CSZ;
    const int s   = cluster_rank();          // slice within image
    const int tid = threadIdx.x;
    const int wid = tid >> 5;
    const int lid = tid & 31;

    // ===== phase A: float4 argmax + labels for rows rbase..rbase+13 (halo) =====
    const int rbase = s*SR - 1;
    const float* basep = outp + (size_t)b * CC * HW;
    const int*   tb    = tgt + (size_t)b * HW;
    if (tid < (SR+2) * (WW/4)) {             // 14 rows * 24 float4 groups = 336
        int li = tid / (WW/4), jv = tid % (WW/4);
        int gi = rbase + li;
        if (gi >= 0 && gi < HH) {
            int idx = gi*WW + jv*4;
            float4 a0 = *(const float4*)(basep + idx);
            float4 a1 = *(const float4*)(basep + idx + HW);
            float4 a2 = *(const float4*)(basep + idx + 2*HW);
            float4 a3 = *(const float4*)(basep + idx + 3*HW);
            int4  t4  = *(const int4*)(tb + idx);
            unsigned lp = (unsigned)amax4(a0.x, a1.x, a2.x, a3.x)
                        | ((unsigned)amax4(a0.y, a1.y, a2.y, a3.y) << 8)
                        | ((unsigned)amax4(a0.z, a1.z, a2.z, a3.z) << 16)
                        | ((unsigned)amax4(a0.w, a1.w, a2.w, a3.w) << 24);
            unsigned lt = (unsigned)t4.x | ((unsigned)t4.y << 8)
                        | ((unsigned)t4.z << 16) | ((unsigned)t4.w << 24);
            *(unsigned*)&labP[li*WW + jv*4] = lp;
            *(unsigned*)&labT[li*WW + jv*4] = lt;
        }
    }
    __syncthreads();

    // ===== phase B: boundary ballots; lanes 0..7 fan the u64 out to 8 ranks =====
    #pragma unroll
    for (int it = 0; it < 2; it++) {
        int sp = it*NWARP + wid;             // span id; 2nd iter: 12 warps idle
        if (sp < NSPAN) {
            int r  = sp / 3;                 // local row 0..11
            int w  = sp % 3;                 // 32-column word index
            int j  = w*32 + lid;
            int gi = s*SR + r;
            int o  = (r + 1)*WW + j;
            int lp = labP[o], lt = labT[o];
            int mp = 0, mt = 0;
            if (gi > 0)    { mp |= labP[o-WW] != lp; mt |= labT[o-WW] != lt; }
            if (gi < HH-1) { mp |= labP[o+WW] != lp; mt |= labT[o+WW] != lt; }
            if (j > 0)     { mp |= labP[o-1]  != lp; mt |= labT[o-1]  != lt; }
            if (j < WW-1)  { mp |= labP[o+1]  != lp; mt |= labT[o+1]  != lt; }
            unsigned wp = __ballot_sync(0xFFFFFFFFu, mp);
            unsigned wt = __ballot_sync(0xFFFFFFFFu, mt);
            if (lid < CSZ) {                 // 8 lanes push in parallel, 1 store each
                unsigned long long v = (unsigned long long)wp
                                     | ((unsigned long long)wt << 32);
                st_cluster_u64(smem_u32(&rmPT[gi*3 + w]), (unsigned)lid, v);
            }
        }
    }

    // ===== single cluster barrier: orders all pushes, all ranks =====
    CLUSTER_SYNC();

    // ===== phase F+G fused: warp w owns row w entirely (3 px/lane) =====
    // vertical EDT -> row smem -> __syncwarp -> horizontal min-plus, no block sync
    int maxF = -1, maxB = -1;
    if (wid < SR) {
        const int r  = wid;
        const int gi = s*SR + r;
        unsigned char* gProw = gPr + r*WW;
        unsigned char* gTrow = gTr + r*WW;
        int dPk[3], dTk[3];
        #pragma unroll
        for (int k = 0; k < 3; k++) {
            int j  = k*32 + lid;
            int wj = k;                      // j>>5 == k
            int bit = lid;
            unsigned long long w0 = rmPT[gi*3 + wj];
            int dP = ((unsigned)(w0 >> bit) & 1u) ? 0 : 255;
            int dT = ((unsigned)(w0 >> (bit + 32)) & 1u) ? 0 : 255;
            #pragma unroll 1
            for (int rr = 1; (dP == 255) | (dT == 255); rr++) {
                bool anyRow = false;
                unsigned long long both = 0;
                if (gi - rr >= 0) { both  = rmPT[(gi-rr)*3 + wj]; anyRow = true; }
                if (gi + rr < HH) { both |= rmPT[(gi+rr)*3 + wj]; anyRow = true; }
                if (!anyRow) break;
                if (dP == 255 && (((unsigned)(both >> bit)) & 1u)) dP = rr;
                if (dT == 255 && (((unsigned)(both >> (bit + 32))) & 1u)) dT = rr;
            }
            gProw[j] = (unsigned char)dP;
            gTrow[j] = (unsigned char)dT;
            dPk[k] = dP; dTk[k] = dT;
        }
        __syncwarp();
        #pragma unroll
        for (int k = 0; k < 3; k++) {
            int j = k*32 + lid;
            if (dPk[k] == 0) maxF = max(maxF, hmin(gTrow, j));  // pred -> tgt
            if (dTk[k] == 0) maxB = max(maxB, hmin(gProw, j));  // tgt -> pred
        }
    }

    // ===== phase H: block reduction, per-image atomicMax, final ticket =====
    #pragma unroll
    for (int sh = 16; sh > 0; sh >>= 1) {
        maxF = max(maxF, __shfl_xor_sync(0xFFFFFFFFu, maxF, sh));
        maxB = max(maxB, __shfl_xor_sync(0xFFFFFFFFu, maxB, sh));
    }
    if (lid == 0) { redF[wid] = maxF; redB[wid] = maxB; }
    __syncthreads();

    if (tid == 0) {
        int f = -1, w = -1;
        #pragma unroll
        for (int k = 0; k < SR; k++) { f = max(f, redF[k]); w = max(w, redB[k]); }
        if (f > 0) atomicMax(&g_fwd[b], f);
        if (w > 0) atomicMax(&g_bwd[b], w);
        __threadfence();
        unsigned ticket = atomicAdd(&g_tick, 1u);
        if (ticket == NBLK - 1) {
            __threadfence();
            float sum = 0.0f;
            #pragma unroll
            for (int k = 0; k < BB; k++) {
                int v = max(max(g_fwd[k], g_bwd[k]), 0);
                float d2 = (v >= 50000) ? 1e10f : (float)v;   // empty-set sentinel
                sum += sqrtf(d2);
            }
            out[0] = sum * (1.0f / BB);
            #pragma unroll
            for (int k = 0; k < BB; k++) { g_fwd[k] = 0; g_bwd[k] = 0; }
            g_tick = 0;
        }
    }
}

extern "C" void kernel_launch(void* const* d_in, const int* in_sizes, int n_in,
                              void* d_out, int out_size) {
    const float* outp = (const float*)d_in[0];   // [B,C,H,W] fp32
    const int*   tgt  = (const int*)d_in[1];     // [B,H,W] int32
    k_all<<<NBLK, NTHR>>>(outp, tgt, (float*)d_out);
}

// round 13
// speedup vs baseline: 1.2610x; 1.2610x over previous
#include <cuda_runtime.h>
#include <cstdint>

#define BB 4
#define CC 4
#define HH 96
#define WW 96
#define HW (HH*WW)
#define CSZ 4             // cluster size = slices per image
#define SR 24             // rows per slice
#define NTHR 768
#define NWARP (NTHR/32)   // 24
#define NBLK (BB*CSZ)     // 16
#define NSPAN (SR*WW/32)  // 72 ballot spans per slice

__device__ int g_fwd[BB];                 // zero at load; finisher resets
__device__ int g_bwd[BB];
__device__ unsigned g_cnt[BB];            // per-image arrival ticket
__device__ unsigned long long g_sum;      // fixed-point sum of sqrts (deterministic)
__device__ unsigned g_tick;               // cross-image ticket

#define CLUSTER_SYNC() do { \
    asm volatile("barrier.cluster.arrive.aligned;" ::: "memory"); \
    asm volatile("barrier.cluster.wait.aligned;" ::: "memory"); } while (0)

__device__ __forceinline__ unsigned smem_u32(const void* p) {
    unsigned a;
    asm("{ .reg .u64 t; cvta.to.shared.u64 t, %1; cvt.u32.u64 %0, t; }"
        : "=r"(a) : "l"(p));
    return a;
}
__device__ __forceinline__ unsigned cluster_rank() {
    unsigned r; asm("mov.u32 %0, %%cluster_ctarank;" : "=r"(r)); return r;
}
__device__ __forceinline__ void st_cluster_u64(unsigned local_addr, unsigned rank,
                                               unsigned long long v) {
    unsigned ra;
    asm("mapa.shared::cluster.u32 %0, %1, %2;" : "=r"(ra) : "r"(local_addr), "r"(rank));
    asm volatile("st.shared::cluster.u64 [%0], %1;" :: "r"(ra), "l"(v) : "memory");
}

// horizontal min-plus with sound early exit: d2 = min_jp (j-jp)^2 + g[jp]^2
__device__ __forceinline__ int hmin(const unsigned char* g, int j) {
    int g0 = g[j];
    int best = g0 * g0;
    #pragma unroll 1
    for (int r = 1; r < WW; r++) {
        int rr = r * r;
        if (rr >= best) break;
        if (j - r >= 0) { int a = g[j - r]; best = min(best, rr + a*a); }
        if (j + r < WW) { int a = g[j + r]; best = min(best, rr + a*a); }
    }
    return best;
}

__device__ __forceinline__ int amax4(float v0, float v1, float v2, float v3) {
    int c = 0; float b = v0;
    if (v1 > b) { b = v1; c = 1; }
    if (v2 > b) { b = v2; c = 2; }
    if (v3 > b) { b = v3; c = 3; }
    return c;
}

__global__ __launch_bounds__(NTHR, 1) __cluster_dims__(CSZ, 1, 1)
void k_all(const float* __restrict__ outp, const int* __restrict__ tgt,
           float* __restrict__ out) {
    __shared__ unsigned char labP[(SR+2)*WW];
    __shared__ unsigned char labT[(SR+2)*WW];
    // full-image row-major masks: rmPT[row*3 + word] = P bits (lo32) | T bits (hi32)
    __shared__ unsigned long long rmPT[HH*3];
    __shared__ unsigned char gPr[SR*WW];
    __shared__ unsigned char gTr[SR*WW];
    __shared__ int redF[NWARP], redB[NWARP];

    const int bb  = blockIdx.x;
    const int b   = bb / CSZ;
    const int s   = cluster_rank();          // slice within image
    const int tid = threadIdx.x;
    const int wid = tid >> 5;
    const int lid = tid & 31;

    // ===== phase A: float4 argmax + labels for rows rbase..rbase+25 (halo) =====
    const int rbase = s*SR - 1;
    const float* basep = outp + (size_t)b * CC * HW;
    const int*   tb    = tgt + (size_t)b * HW;
    if (tid < (SR+2) * (WW/4)) {             // 26 rows * 24 float4 groups = 624
        int li = tid / (WW/4), jv = tid % (WW/4);
        int gi = rbase + li;
        if (gi >= 0 && gi < HH) {
            int idx = gi*WW + jv*4;
            float4 a0 = *(const float4*)(basep + idx);
            float4 a1 = *(const float4*)(basep + idx + HW);
            float4 a2 = *(const float4*)(basep + idx + 2*HW);
            float4 a3 = *(const float4*)(basep + idx + 3*HW);
            int4  t4  = *(const int4*)(tb + idx);
            unsigned lp = (unsigned)amax4(a0.x, a1.x, a2.x, a3.x)
                        | ((unsigned)amax4(a0.y, a1.y, a2.y, a3.y) << 8)
                        | ((unsigned)amax4(a0.z, a1.z, a2.z, a3.z) << 16)
                        | ((unsigned)amax4(a0.w, a1.w, a2.w, a3.w) << 24);
            unsigned lt = (unsigned)t4.x | ((unsigned)t4.y << 8)
                        | ((unsigned)t4.z << 16) | ((unsigned)t4.w << 24);
            *(unsigned*)&labP[li*WW + jv*4] = lp;
            *(unsigned*)&labT[li*WW + jv*4] = lt;
        }
    }
    __syncthreads();

    // ===== phase B: boundary ballots; lanes 0..3 fan the u64 out to 4 ranks =====
    #pragma unroll
    for (int it = 0; it < NSPAN/NWARP; it++) {   // 3 iterations, sp < 72 always
        int sp = it*NWARP + wid;
        int r  = sp / 3;                     // local row 0..23
        int w  = sp % 3;                     // 32-column word index
        int j  = w*32 + lid;
        int gi = s*SR + r;
        int o  = (r + 1)*WW + j;
        int lp = labP[o], lt = labT[o];
        int mp = 0, mt = 0;
        if (gi > 0)    { mp |= labP[o-WW] != lp; mt |= labT[o-WW] != lt; }
        if (gi < HH-1) { mp |= labP[o+WW] != lp; mt |= labT[o+WW] != lt; }
        if (j > 0)     { mp |= labP[o-1]  != lp; mt |= labT[o-1]  != lt; }
        if (j < WW-1)  { mp |= labP[o+1]  != lp; mt |= labT[o+1]  != lt; }
        unsigned wp = __ballot_sync(0xFFFFFFFFu, mp);
        unsigned wt = __ballot_sync(0xFFFFFFFFu, mt);
        if (lid < CSZ) {                     // 4 lanes push in parallel, 1 store each
            unsigned long long v = (unsigned long long)wp
                                 | ((unsigned long long)wt << 32);
            st_cluster_u64(smem_u32(&rmPT[gi*3 + w]), (unsigned)lid, v);
        }
    }

    // ===== single cluster barrier: orders all pushes, all ranks =====
    CLUSTER_SYNC();

    // ===== phase F+G fused: warp w owns row w entirely (3 px/lane) =====
    int maxF = -1, maxB = -1;
    {
        const int r  = wid;                  // 24 warps, 24 rows
        const int gi = s*SR + r;
        unsigned char* gProw = gPr + r*WW;
        unsigned char* gTrow = gTr + r*WW;
        int dPk[3], dTk[3];
        #pragma unroll
        for (int k = 0; k < 3; k++) {
            int j  = k*32 + lid;
            int bit = lid;
            unsigned long long w0 = rmPT[gi*3 + k];
            int dP = ((unsigned)(w0 >> bit) & 1u) ? 0 : 255;
            int dT = ((unsigned)(w0 >> (bit + 32)) & 1u) ? 0 : 255;
            #pragma unroll 1
            for (int rr = 1; (dP == 255) | (dT == 255); rr++) {
                bool anyRow = false;
                unsigned long long both = 0;
                if (gi - rr >= 0) { both  = rmPT[(gi-rr)*3 + k]; anyRow = true; }
                if (gi + rr < HH) { both |= rmPT[(gi+rr)*3 + k]; anyRow = true; }
                if (!anyRow) break;
                if (dP == 255 && (((unsigned)(both >> bit)) & 1u)) dP = rr;
                if (dT == 255 && (((unsigned)(both >> (bit + 32))) & 1u)) dT = rr;
            }
            gProw[j] = (unsigned char)dP;
            gTrow[j] = (unsigned char)dT;
            dPk[k] = dP; dTk[k] = dT;
        }
        __syncwarp();
        #pragma unroll
        for (int k = 0; k < 3; k++) {
            int j = k*32 + lid;
            if (dPk[k] == 0) maxF = max(maxF, hmin(gTrow, j));  // pred -> tgt
            if (dTk[k] == 0) maxB = max(maxB, hmin(gProw, j));  // tgt -> pred
        }
    }

    // ===== phase H: block reduce -> per-image finisher -> fixed-point sum =====
    #pragma unroll
    for (int sh = 16; sh > 0; sh >>= 1) {
        maxF = max(maxF, __shfl_xor_sync(0xFFFFFFFFu, maxF, sh));
        maxB = max(maxB, __shfl_xor_sync(0xFFFFFFFFu, maxB, sh));
    }
    if (lid == 0) { redF[wid] = maxF; redB[wid] = maxB; }
    __syncthreads();

    if (tid == 0) {
        int f = -1, w = -1;
        #pragma unroll
        for (int k = 0; k < NWARP; k++) { f = max(f, redF[k]); w = max(w, redB[k]); }
        if (f > 0) atomicMax(&g_fwd[b], f);
        if (w > 0) atomicMax(&g_bwd[b], w);
        __threadfence();
        unsigned t1 = atomicAdd(&g_cnt[b], 1u);
        if (t1 == CSZ - 1) {                 // this CTA finishes image b
            int fa = atomicMax(&g_fwd[b], 0);    // atomic read (values >= 0)
            int wa = atomicMax(&g_bwd[b], 0);
            g_fwd[b] = 0; g_bwd[b] = 0; g_cnt[b] = 0;   // reset for next replay
            int v = max(max(fa, wa), 0);
            float d2 = (v >= 50000) ? 1e10f : (float)v;  // empty-set sentinel
            // fixed-point (2^20) integer add: order-independent => deterministic
            unsigned long long scaled =
                (unsigned long long)(sqrtf(d2) * 1048576.0f);
            atomicAdd(&g_sum, scaled);
            __threadfence();
            unsigned t2 = atomicAdd(&g_tick, 1u);
            if (t2 == BB - 1) {              // last image finisher writes output
                unsigned long long ssum = atomicAdd(&g_sum, 0ULL);
                out[0] = (float)((double)ssum * (1.0 / (1048576.0 * BB)));
                g_sum = 0; g_tick = 0;       // reset for next replay
            }
        }
    }
}

extern "C" void kernel_launch(void* const* d_in, const int* in_sizes, int n_in,
                              void* d_out, int out_size) {
    const float* outp = (const float*)d_in[0];   // [B,C,H,W] fp32
    const int*   tgt  = (const int*)d_in[1];     // [B,H,W] int32
    k_all<<<NBLK, NTHR>>>(outp, tgt, (float*)d_out);
}